// round 14
// baseline (speedup 1.0000x reference)
#include <cuda_runtime.h>
#include <cuda_bf16.h>
#include <cstdint>

#define Bn 64
#define Qn 2048
#define Kn 2048
#define Dn 128

// ---------------- scratch (device globals; no allocation) ----------------
__device__ __align__(256) __nv_bfloat16 g_qh[(size_t)Bn * Qn * Dn];
__device__ __align__(256) __nv_bfloat16 g_ql[(size_t)Bn * Qn * Dn];
__device__ __align__(256) __nv_bfloat16 g_kh[(size_t)Bn * Kn * Dn];
__device__ __align__(256) __nv_bfloat16 g_kl[(size_t)Bn * Kn * Dn];
__device__ __align__(256) __nv_bfloat16 g_vth[(size_t)Bn * Dn * Kn];  // [b][d][k]
__device__ __align__(256) __nv_bfloat16 g_vtl[(size_t)Bn * Dn * Kn];
__device__ __align__(256) float g_ps[(size_t)Bn * Qn * 64];   // partial sums per 32-col block
__device__ __align__(256) float g_is[(size_t)Bn * Qn];        // 1/row sum

// ---------------- helpers ----------------
#define MMA_BF16(C, a0, a1, a2, a3, b0, b1)                                   \
  asm volatile(                                                               \
      "mma.sync.aligned.m16n8k16.row.col.f32.bf16.bf16.f32 "                  \
      "{%0,%1,%2,%3}, {%4,%5,%6,%7}, {%8,%9}, {%0,%1,%2,%3};\n"               \
      : "+f"(C[0]), "+f"(C[1]), "+f"(C[2]), "+f"(C[3])                        \
      : "r"(a0), "r"(a1), "r"(a2), "r"(a3), "r"(b0), "r"(b1))

#define LDSM_X4(r0, r1, r2, r3, a)                                            \
  asm volatile("ldmatrix.sync.aligned.m8n8.x4.shared.b16 {%0,%1,%2,%3}, [%4];" \
               : "=r"(r0), "=r"(r1), "=r"(r2), "=r"(r3) : "r"(a))

__device__ __forceinline__ void splitpack(float x, float y, uint32_t& h, uint32_t& l) {
    __nv_bfloat162 hh = __floats2bfloat162_rn(x, y);
    float hx = __low2float(hh);
    float hy = __high2float(hh);
    __nv_bfloat162 ll = __floats2bfloat162_rn(x - hx, y - hy);
    h = *reinterpret_cast<uint32_t*>(&hh);
    l = *reinterpret_cast<uint32_t*>(&ll);
}
__device__ __forceinline__ uint32_t smem_u32(const void* p) {
    return (uint32_t)__cvta_generic_to_shared(p);
}
__device__ __forceinline__ void cpasync16(uint32_t dst, const void* src) {
    asm volatile("cp.async.cg.shared.global [%0], [%1], 16;\n" :: "r"(dst), "l"(src));
}
#define CP_COMMIT asm volatile("cp.async.commit_group;\n" ::: "memory")
#define CP_WAIT0  asm volatile("cp.async.wait_group 0;\n" ::: "memory")

// ================= K0a: fp32 -> (hi, lo) bf16 =================
__global__ void __launch_bounds__(256)
convert_kernel(const float* __restrict__ x, __nv_bfloat16* __restrict__ h,
               __nv_bfloat16* __restrict__ l)
{
    int i = blockIdx.x * 256 + threadIdx.x;
    float4 v = ((const float4*)x)[i];
    uint32_t h0, l0, h1, l1;
    splitpack(v.x, v.y, h0, l0);
    splitpack(v.z, v.w, h1, l1);
    ((uint2*)h)[i] = make_uint2(h0, h1);
    ((uint2*)l)[i] = make_uint2(l0, l1);
}

// ================= K0b: V fp32 [b][k][d] -> bf16 hi/lo [b][d][k] =================
__global__ void __launch_bounds__(256)
transpose_conv_kernel(const float* __restrict__ v,
                      __nv_bfloat16* __restrict__ th, __nv_bfloat16* __restrict__ tl)
{
    __shared__ float t[32][33];
    const int b  = blockIdx.z;
    const int k0 = blockIdx.x * 32;
    const int d0 = blockIdx.y * 32;
    const int tx = threadIdx.x & 31;
    const int ty = threadIdx.x >> 5;
#pragma unroll
    for (int i = 0; i < 4; i++) {
        int k = ty + i * 8;
        t[k][tx] = v[((size_t)b * Kn + k0 + k) * Dn + d0 + tx];
    }
    __syncthreads();
#pragma unroll
    for (int i = 0; i < 4; i++) {
        int d = ty + i * 8;
        float x = t[tx][d];
        __nv_bfloat16 hb = __float2bfloat16_rn(x);
        __nv_bfloat16 lb = __float2bfloat16_rn(x - __bfloat162float(hb));
        size_t o = ((size_t)b * Dn + d0 + d) * Kn + k0 + tx;
        th[o] = hb;
        tl[o] = lb;
    }
}

// ================= K1: E = exp(masked scores) fp32 + partial row sums =================
// 256 threads, CTA tile M=64 x N=128, 104.4KB smem -> 2 CTAs/SM (cross-CTA overlap).
#define K1S 136                        /* bf16 row stride (272 B) */
#define OFF_QH 0
#define OFF_QL (64 * K1S * 2)          /* 17408 */
#define OFF_KH (2 * 64 * K1S * 2)      /* 34816 */
#define OFF_KL (OFF_KH + 128 * K1S * 2)/* 69632 */
#define K1_SMEM (OFF_KL + 128 * K1S * 2) /* 104448 */
#define SC_SCALE 0.08838834764831845f

__global__ void __launch_bounds__(256, 2)
scores_kernel(const __nv_bfloat16* __restrict__ qh, const __nv_bfloat16* __restrict__ ql,
              const __nv_bfloat16* __restrict__ kh, const __nv_bfloat16* __restrict__ kl,
              const int* __restrict__ vlg,
              float* __restrict__ eg, float* __restrict__ ps)
{
    extern __shared__ unsigned char sm[];
    const uint32_t base = smem_u32(sm);
    const uint32_t uQh = base + OFF_QH, uQl = base + OFF_QL;
    const uint32_t uKh = base + OFF_KH, uKl = base + OFF_KL;

    const int b  = blockIdx.z;
    const int i0 = blockIdx.y * 64;
    const int j0 = blockIdx.x * 128;
    const int tid = threadIdx.x;
    const int w = tid >> 5, lane = tid & 31;
    const int g = lane >> 2, ct = lane & 3;
    const int wm = w >> 2, wn = w & 3;        // 2(m) x 4(n) warp grid, 32x32 warp tiles
    const int m0 = wm * 32, n0 = wn * 32;
    const int VL = vlg[b];

    const __nv_bfloat16* bq_h = qh + ((size_t)b * Qn + i0) * Dn;
    const __nv_bfloat16* bq_l = ql + ((size_t)b * Qn + i0) * Dn;
    const __nv_bfloat16* bk_h = kh + ((size_t)b * Kn + j0) * Dn;
    const __nv_bfloat16* bk_l = kl + ((size_t)b * Kn + j0) * Dn;

    // 4 commit groups, one per D-quarter (cols q*32 .. q*32+31)
#pragma unroll
    for (int q = 0; q < 4; q++) {
        {   // Q hi/lo: 64 rows x 4 chunks = 256 ops each
            int r = tid >> 2, cc = tid & 3;
            int dsto = r * (K1S * 2) + (q * 4 + cc) * 16;
            size_t srco = (size_t)r * Dn + q * 32 + cc * 8;
            cpasync16(uQh + dsto, bq_h + srco);
            cpasync16(uQl + dsto, bq_l + srco);
        }
#pragma unroll
        for (int rep = 0; rep < 2; rep++) {   // K hi/lo: 128 rows x 4 = 512 ops each
            int idx = tid + rep * 256;
            int r = idx >> 2, cc = idx & 3;
            int dsto = r * (K1S * 2) + (q * 4 + cc) * 16;
            size_t srco = (size_t)r * Dn + q * 32 + cc * 8;
            cpasync16(uKh + dsto, bk_h + srco);
            cpasync16(uKl + dsto, bk_l + srco);
        }
        CP_COMMIT;
    }

    // ldmatrix per-thread base addresses
    const int lr = lane & 15;
    const int lc = (lane >> 4) << 3;
    const uint32_t aQh = uQh + ((m0 + lr) * K1S + lc) * 2;
    const uint32_t aQl = uQl + ((m0 + lr) * K1S + lc) * 2;
    const uint32_t aKh = uKh + ((n0 + lr) * K1S + lc) * 2;
    const uint32_t aKl = uKl + ((n0 + lr) * K1S + lc) * 2;
    const uint32_t MSTEP = 16 * K1S * 2;   // 4352 bytes per 16 rows

    float acc[2][4][4] = {};
#pragma unroll
    for (int q = 0; q < 4; q++) {
        if (q == 0)      asm volatile("cp.async.wait_group 3;\n" ::: "memory");
        else if (q == 1) asm volatile("cp.async.wait_group 2;\n" ::: "memory");
        else if (q == 2) asm volatile("cp.async.wait_group 1;\n" ::: "memory");
        else             asm volatile("cp.async.wait_group 0;\n" ::: "memory");
        __syncthreads();
#pragma unroll
        for (int kt = 0; kt < 2; kt++) {
            const uint32_t co = (q * 2 + kt) * 32;   // 16 bf16 = 32 bytes per k-step
            uint32_t ah[2][4], al[2][4], bh[2][4], bl[2][4];
            LDSM_X4(ah[0][0], ah[0][1], ah[0][2], ah[0][3], aQh + co);
            LDSM_X4(ah[1][0], ah[1][1], ah[1][2], ah[1][3], aQh + MSTEP + co);
            LDSM_X4(al[0][0], al[0][1], al[0][2], al[0][3], aQl + co);
            LDSM_X4(al[1][0], al[1][1], al[1][2], al[1][3], aQl + MSTEP + co);
            LDSM_X4(bh[0][0], bh[0][1], bh[0][2], bh[0][3], aKh + co);
            LDSM_X4(bh[1][0], bh[1][1], bh[1][2], bh[1][3], aKh + MSTEP + co);
            LDSM_X4(bl[0][0], bl[0][1], bl[0][2], bl[0][3], aKl + co);
            LDSM_X4(bl[1][0], bl[1][1], bl[1][2], bl[1][3], aKl + MSTEP + co);
            // term-major: 8 independent MMAs per term
#pragma unroll
            for (int q2 = 0; q2 < 2; q2++)       // term 1: hi*hi
#pragma unroll
                for (int h2 = 0; h2 < 2; h2++)
#pragma unroll
                    for (int mf = 0; mf < 2; mf++)
                        MMA_BF16(acc[mf][2 * q2 + h2],
                                 ah[mf][0], ah[mf][1], ah[mf][2], ah[mf][3],
                                 bh[q2][h2], bh[q2][h2 + 2]);
#pragma unroll
            for (int q2 = 0; q2 < 2; q2++)       // term 2: hi*lo
#pragma unroll
                for (int h2 = 0; h2 < 2; h2++)
#pragma unroll
                    for (int mf = 0; mf < 2; mf++)
                        MMA_BF16(acc[mf][2 * q2 + h2],
                                 ah[mf][0], ah[mf][1], ah[mf][2], ah[mf][3],
                                 bl[q2][h2], bl[q2][h2 + 2]);
#pragma unroll
            for (int q2 = 0; q2 < 2; q2++)       // term 3: lo*hi
#pragma unroll
                for (int h2 = 0; h2 < 2; h2++)
#pragma unroll
                    for (int mf = 0; mf < 2; mf++)
                        MMA_BF16(acc[mf][2 * q2 + h2],
                                 al[mf][0], al[mf][1], al[mf][2], al[mf][3],
                                 bh[q2][h2], bh[q2][h2 + 2]);
        }
    }

    // ---- epilogue: scale, mask, exp, fp32 E store, partial sums ----
    const float mval = (VL == 0) ? 1.0f : 0.0f;
    const int jt = blockIdx.x * 4 + wn;        // 32-col block id (0..63)
#pragma unroll
    for (int mf = 0; mf < 2; mf++) {
#pragma unroll
        for (int h = 0; h < 2; h++) {
            const int row = m0 + mf * 16 + h * 8 + g;
            float* erow = eg + ((size_t)b * Qn + i0 + row) * Kn + j0 + n0;
            float se = 0.f;
#pragma unroll
            for (int nf = 0; nf < 4; nf++) {
                int j = j0 + n0 + nf * 8 + 2 * ct;
                float e0 = (j     < VL) ? __expf(acc[mf][nf][2 * h]     * SC_SCALE) : mval;
                float e1 = (j + 1 < VL) ? __expf(acc[mf][nf][2 * h + 1] * SC_SCALE) : mval;
                *(float2*)(erow + nf * 8 + 2 * ct) = make_float2(e0, e1);
                se += e0 + e1;
            }
            se += __shfl_xor_sync(0xffffffffu, se, 1);
            se += __shfl_xor_sync(0xffffffffu, se, 2);
            if (ct == 0)
                ps[((size_t)b * Qn + i0 + row) * 64 + jt] = se;
        }
    }
}

// ================= K1b: reduce partials -> 1/row sum =================
__global__ void __launch_bounds__(256)
reduce_kernel(const float* __restrict__ ps, float* __restrict__ iso)
{
    int i = blockIdx.x * 256 + threadIdx.x;
    const float4* s4 = (const float4*)(ps + (size_t)i * 64);
    float sum = 0.f;
#pragma unroll
    for (int t = 0; t < 16; t++) {
        float4 sv = s4[t];
        sum += (sv.x + sv.y) + (sv.z + sv.w);
    }
    iso[i] = 1.0f / sum;
}

// ================= K2: normalize + attn writeback + PV GEMM (R7-measured best) =================
#define PS 68     /* float stride, E tile (k-contiguous) */
#define VS 72     /* bf16 stride, Vt tile rows d, cols k  */
#define K2_OFF_S  0
#define K2_SZ_S   (128 * PS * 4)          /* 34816 */
#define K2_OFF_VH (K2_SZ_S)
#define K2_SZ_V   (128 * VS * 2)          /* 18432 */
#define K2_OFF_VL (K2_OFF_VH + K2_SZ_V)
#define K2_OFF_IV (K2_OFF_VL + K2_SZ_V)
#define K2_SMEM   (K2_OFF_IV + 128 * 4)   /* 72192 */

__global__ void __launch_bounds__(256, 2)
pv_kernel(float* __restrict__ att,                     // in: E values, out: attn
          const __nv_bfloat16* __restrict__ vth, const __nv_bfloat16* __restrict__ vtl,
          const float* __restrict__ isg,
          float* __restrict__ outg)
{
    extern __shared__ unsigned char sm[];
    float*         sS  = (float*)(sm + K2_OFF_S);
    __nv_bfloat16* sVh = (__nv_bfloat16*)(sm + K2_OFF_VH);
    __nv_bfloat16* sVl = (__nv_bfloat16*)(sm + K2_OFF_VL);
    float*         sIv = (float*)(sm + K2_OFF_IV);

    const int b  = blockIdx.y;
    const int i0 = blockIdx.x * 128;
    const int tid = threadIdx.x;
    const int w = tid >> 5, lane = tid & 31;
    const int g = lane >> 2, ct = lane & 3;
    const int wm = w >> 1, wn = w & 1;

    float* Sg = att + ((size_t)b * Qn + i0) * Kn;
    const __nv_bfloat16* vh_g = vth + (size_t)b * Dn * Kn;
    const __nv_bfloat16* vl_g = vtl + (size_t)b * Dn * Kn;
    uint32_t sS_u  = smem_u32(sS);
    uint32_t sVh_u = smem_u32(sVh);
    uint32_t sVl_u = smem_u32(sVl);

    if (tid < 128) sIv[tid] = isg[(size_t)b * Qn + i0 + tid];

    float ris[2][2];
#pragma unroll
    for (int mf = 0; mf < 2; mf++)
#pragma unroll
        for (int h = 0; h < 2; h++)
            ris[mf][h] = isg[(size_t)b * Qn + i0 + wm * 32 + mf * 16 + h * 8 + g];

    float acc[2][8][4] = {};

    for (int c0 = 0; c0 < Kn; c0 += 64) {
        __syncthreads();
#pragma unroll
        for (int rep = 0; rep < 8; rep++) {
            int idx = tid + rep * 256;
            int r = idx >> 4, c4 = idx & 15;
            cpasync16(sS_u + r * (PS * 4) + c4 * 16, Sg + (size_t)r * Kn + c0 + c4 * 4);
        }
#pragma unroll
        for (int rep = 0; rep < 8; rep++) {
            int arr = rep >> 2;
            int rem = tid + (rep & 3) * 256;
            int d = rem >> 3, c4 = rem & 7;
            if (arr == 0)
                cpasync16(sVh_u + d * (VS * 2) + c4 * 16, vh_g + (size_t)d * Kn + c0 + c4 * 8);
            else
                cpasync16(sVl_u + d * (VS * 2) + c4 * 16, vl_g + (size_t)d * Kn + c0 + c4 * 8);
        }
        CP_COMMIT; CP_WAIT0;
        __syncthreads();

        // normalized-attn writeback (each element exactly once, coalesced)
#pragma unroll
        for (int rep = 0; rep < 8; rep++) {
            int idx = tid + rep * 256;
            int r = idx >> 4, c4 = idx & 15;
            float iv = sIv[r];
            float4 e = *(const float4*)(sS + r * PS + c4 * 4);
            e.x *= iv; e.y *= iv; e.z *= iv; e.w *= iv;
            *(float4*)(Sg + (size_t)r * Kn + c0 + c4 * 4) = e;
        }

#pragma unroll
        for (int kk = 0; kk < 4; kk++) {
            uint32_t ah[2][4], al[2][4];
#pragma unroll
            for (int mf = 0; mf < 2; mf++) {
                const float* sp = sS + (wm * 32 + mf * 16 + g) * PS + kk * 16 + 2 * ct;
                float2 s0 = *(const float2*)sp;
                float2 s1 = *(const float2*)(sp + 8 * PS);
                float2 s2 = *(const float2*)(sp + 8);
                float2 s3 = *(const float2*)(sp + 8 * PS + 8);
                float i0v = ris[mf][0], i1v = ris[mf][1];
                splitpack(s0.x * i0v, s0.y * i0v, ah[mf][0], al[mf][0]);
                splitpack(s1.x * i1v, s1.y * i1v, ah[mf][1], al[mf][1]);
                splitpack(s2.x * i0v, s2.y * i0v, ah[mf][2], al[mf][2]);
                splitpack(s3.x * i1v, s3.y * i1v, ah[mf][3], al[mf][3]);
            }
#pragma unroll
            for (int nf = 0; nf < 8; nf++) {
                const __nv_bfloat16* vb = sVh + (wn * 64 + nf * 8 + g) * VS + kk * 16 + 2 * ct;
                uint32_t bh0 = *(const uint32_t*)vb;
                uint32_t bh1 = *(const uint32_t*)(vb + 8);
                const __nv_bfloat16* vc = sVl + (wn * 64 + nf * 8 + g) * VS + kk * 16 + 2 * ct;
                uint32_t bl0 = *(const uint32_t*)vc;
                uint32_t bl1 = *(const uint32_t*)(vc + 8);
#pragma unroll
                for (int mf = 0; mf < 2; mf++) {
                    MMA_BF16(acc[mf][nf], ah[mf][0], ah[mf][1], ah[mf][2], ah[mf][3], bh0, bh1);
                    MMA_BF16(acc[mf][nf], ah[mf][0], ah[mf][1], ah[mf][2], ah[mf][3], bl0, bl1);
                    MMA_BF16(acc[mf][nf], al[mf][0], al[mf][1], al[mf][2], al[mf][3], bh0, bh1);
                }
            }
        }
    }

    float* op = outg + ((size_t)b * Qn + i0) * Dn;
#pragma unroll
    for (int mf = 0; mf < 2; mf++)
#pragma unroll
        for (int nf = 0; nf < 8; nf++) {
            int row = wm * 32 + mf * 16 + g;
            int col = wn * 64 + nf * 8 + 2 * ct;
            *(float2*)(op + (size_t)row * Dn + col)       = make_float2(acc[mf][nf][0], acc[mf][nf][1]);
            *(float2*)(op + (size_t)(row + 8) * Dn + col) = make_float2(acc[mf][nf][2], acc[mf][nf][3]);
        }
}

// ================= launch =================
extern "C" void kernel_launch(void* const* d_in, const int* in_sizes, int n_in,
                              void* d_out, int out_size) {
    const float* q  = (const float*)d_in[0];
    const float* k  = (const float*)d_in[1];
    const float* v  = (const float*)d_in[2];
    const int*   vl = (const int*)d_in[3];
    float* out  = (float*)d_out;
    float* attn = out + (size_t)Bn * Qn * Dn;   // output tuple: (out, attn)

    void *p_qh, *p_ql, *p_kh, *p_kl, *p_vth, *p_vtl, *p_ps, *p_is;
    cudaGetSymbolAddress(&p_qh, g_qh);
    cudaGetSymbolAddress(&p_ql, g_ql);
    cudaGetSymbolAddress(&p_kh, g_kh);
    cudaGetSymbolAddress(&p_kl, g_kl);
    cudaGetSymbolAddress(&p_vth, g_vth);
    cudaGetSymbolAddress(&p_vtl, g_vtl);
    cudaGetSymbolAddress(&p_ps, g_ps);
    cudaGetSymbolAddress(&p_is, g_is);

    cudaFuncSetAttribute(scores_kernel, cudaFuncAttributeMaxDynamicSharedMemorySize, K1_SMEM);
    cudaFuncSetAttribute(pv_kernel,     cudaFuncAttributeMaxDynamicSharedMemorySize, K2_SMEM);

    const int n4 = Bn * Qn * Dn / 4;
    convert_kernel<<<n4 / 256, 256>>>(q, (__nv_bfloat16*)p_qh, (__nv_bfloat16*)p_ql);
    convert_kernel<<<n4 / 256, 256>>>(k, (__nv_bfloat16*)p_kh, (__nv_bfloat16*)p_kl);
    transpose_conv_kernel<<<dim3(Kn / 32, Dn / 32, Bn), 256>>>(v, (__nv_bfloat16*)p_vth,
                                                               (__nv_bfloat16*)p_vtl);

    scores_kernel<<<dim3(Kn / 128, Qn / 64, Bn), 256, K1_SMEM>>>(
        (const __nv_bfloat16*)p_qh, (const __nv_bfloat16*)p_ql,
        (const __nv_bfloat16*)p_kh, (const __nv_bfloat16*)p_kl,
        vl, attn, (float*)p_ps);

    reduce_kernel<<<Bn * Qn / 256, 256>>>((const float*)p_ps, (float*)p_is);

    pv_kernel<<<dim3(Qn / 128, Bn), 256, K2_SMEM>>>(
        attn, (const __nv_bfloat16*)p_vth, (const __nv_bfloat16*)p_vtl,
        (const float*)p_is, out);
}

// round 15
// speedup vs baseline: 1.2717x; 1.2717x over previous
#include <cuda_runtime.h>
#include <cuda_fp16.h>
#include <cstdint>

#define Bn 64
#define Qn 2048
#define Kn 2048
#define Dn 128

// ---------------- scratch (device globals; no allocation) ----------------
__device__ __align__(256) __half g_qh[(size_t)Bn * Qn * Dn];          // Q fp16 (single)
__device__ __align__(256) __half g_kh[(size_t)Bn * Kn * Dn];          // K fp16 hi
__device__ __align__(256) __half g_kl[(size_t)Bn * Kn * Dn];          // K fp16 lo
__device__ __align__(256) __half g_vth[(size_t)Bn * Dn * Kn];         // V^T fp16 hi [b][d][k]
__device__ __align__(256) __half g_vtl[(size_t)Bn * Dn * Kn];         // V^T fp16 lo
__device__ __align__(256) float g_ps[(size_t)Bn * Qn * 32];   // partial sums per 64-col block
__device__ __align__(256) float g_is[(size_t)Bn * Qn];        // 1/row sum

// ---------------- helpers ----------------
#define MMA_F16(C, a0, a1, a2, a3, b0, b1)                                    \
  asm volatile(                                                               \
      "mma.sync.aligned.m16n8k16.row.col.f32.f16.f16.f32 "                    \
      "{%0,%1,%2,%3}, {%4,%5,%6,%7}, {%8,%9}, {%0,%1,%2,%3};\n"               \
      : "+f"(C[0]), "+f"(C[1]), "+f"(C[2]), "+f"(C[3])                        \
      : "r"(a0), "r"(a1), "r"(a2), "r"(a3), "r"(b0), "r"(b1))

__device__ __forceinline__ uint32_t packh2(float x, float y) {
    __half2 h = __floats2half2_rn(x, y);
    return *reinterpret_cast<uint32_t*>(&h);
}
// fp16 hi/lo split of two floats
__device__ __forceinline__ void splith(float x, float y, uint32_t& h, uint32_t& l) {
    __half2 hh = __floats2half2_rn(x, y);
    float hx = __low2float(hh);
    float hy = __high2float(hh);
    __half2 ll = __floats2half2_rn(x - hx, y - hy);
    h = *reinterpret_cast<uint32_t*>(&hh);
    l = *reinterpret_cast<uint32_t*>(&ll);
}
__device__ __forceinline__ uint32_t smem_u32(const void* p) {
    return (uint32_t)__cvta_generic_to_shared(p);
}
__device__ __forceinline__ void cpasync16(uint32_t dst, const void* src) {
    asm volatile("cp.async.cg.shared.global [%0], [%1], 16;\n" :: "r"(dst), "l"(src));
}
#define CP_COMMIT asm volatile("cp.async.commit_group;\n" ::: "memory")
#define CP_WAIT0  asm volatile("cp.async.wait_group 0;\n" ::: "memory")

// ================= K0a: fp32 -> single fp16 =================
__global__ void __launch_bounds__(256)
convert1_kernel(const float* __restrict__ x, __half* __restrict__ h)
{
    int i = blockIdx.x * 256 + threadIdx.x;
    float4 v = ((const float4*)x)[i];
    ((uint2*)h)[i] = make_uint2(packh2(v.x, v.y), packh2(v.z, v.w));
}

// ================= K0b: fp32 -> (hi, lo) fp16 =================
__global__ void __launch_bounds__(256)
convert2_kernel(const float* __restrict__ x, __half* __restrict__ h,
                __half* __restrict__ l)
{
    int i = blockIdx.x * 256 + threadIdx.x;
    float4 v = ((const float4*)x)[i];
    uint32_t h0, l0, h1, l1;
    splith(v.x, v.y, h0, l0);
    splith(v.z, v.w, h1, l1);
    ((uint2*)h)[i] = make_uint2(h0, h1);
    ((uint2*)l)[i] = make_uint2(l0, l1);
}

// ================= K0c: V fp32 [b][k][d] -> fp16 hi/lo [b][d][k] =================
__global__ void __launch_bounds__(256)
transpose_conv_kernel(const float* __restrict__ v,
                      __half* __restrict__ th, __half* __restrict__ tl)
{
    __shared__ float t[32][33];
    const int b  = blockIdx.z;
    const int k0 = blockIdx.x * 32;
    const int d0 = blockIdx.y * 32;
    const int tx = threadIdx.x & 31;
    const int ty = threadIdx.x >> 5;
#pragma unroll
    for (int i = 0; i < 4; i++) {
        int k = ty + i * 8;
        t[k][tx] = v[((size_t)b * Kn + k0 + k) * Dn + d0 + tx];
    }
    __syncthreads();
#pragma unroll
    for (int i = 0; i < 4; i++) {
        int d = ty + i * 8;
        float x = t[tx][d];
        __half hb = __float2half_rn(x);
        __half lb = __float2half_rn(x - __half2float(hb));
        size_t o = ((size_t)b * Dn + d0 + d) * Kn + k0 + tx;
        th[o] = hb;
        tl[o] = lb;
    }
}

// ================= K1: E = exp(masked scores) fp32 + partial row sums =================
// R7 skeleton: 512 threads, CTA tile M=128 x N=256, 4-quarter cp.async pipeline,
// manual LDS frag loads, 2-term fp16 mma (qh*kh + qh*kl).
#define K1S 136                    /* fp16 row stride (272 B) */
#define OFF_QH 0
#define OFF_KH (128 * K1S * 2)                 /* 34816 */
#define OFF_KL (OFF_KH + 256 * K1S * 2)        /* 104448 */
#define K1_SMEM (OFF_KL + 256 * K1S * 2)       /* 174080 */
#define SC_SCALE 0.08838834764831845f

__global__ void __launch_bounds__(512, 1)
scores_kernel(const __half* __restrict__ qh, const __half* __restrict__ kh,
              const __half* __restrict__ kl, const int* __restrict__ vlg,
              float* __restrict__ eg, float* __restrict__ ps)
{
    extern __shared__ unsigned char sm[];
    __half* sQh = (__half*)(sm + OFF_QH);
    __half* sKh = (__half*)(sm + OFF_KH);
    __half* sKl = (__half*)(sm + OFF_KL);
    const uint32_t uQh = smem_u32(sQh), uKh = smem_u32(sKh), uKl = smem_u32(sKl);

    const int b  = blockIdx.z;
    const int i0 = blockIdx.y * 128;
    const int j0 = blockIdx.x * 256;
    const int tid = threadIdx.x;
    const int w = tid >> 5, lane = tid & 31;
    const int g = lane >> 2, ct = lane & 3;
    const int wm = w >> 2, wn = w & 3;        // 4x4 warp grid, 32x64 warp tiles
    const int m0 = wm * 32, n0 = wn * 64;
    const int VL = vlg[b];

    const __half* bq = qh + ((size_t)b * Qn + i0) * Dn;
    const __half* bkh = kh + ((size_t)b * Kn + j0) * Dn;
    const __half* bkl = kl + ((size_t)b * Kn + j0) * Dn;

    // 4 commit groups, one per D-quarter (cols q*32 .. q*32+31)
#pragma unroll
    for (int q = 0; q < 4; q++) {
        {   // Qh: 512 ops
            int r = tid >> 2, cc = tid & 3;
            int dsto = r * (K1S * 2) + (q * 4 + cc) * 16;
            cpasync16(uQh + dsto, bq + (size_t)r * Dn + q * 32 + cc * 8);
        }
#pragma unroll
        for (int rep = 0; rep < 2; rep++) {   // Kh, Kl: 1024 ops each
            int idx = tid + rep * 512;
            int r = idx >> 2, cc = idx & 3;
            int dsto = r * (K1S * 2) + (q * 4 + cc) * 16;
            size_t srco = (size_t)r * Dn + q * 32 + cc * 8;
            cpasync16(uKh + dsto, bkh + srco);
            cpasync16(uKl + dsto, bkl + srco);
        }
        CP_COMMIT;
    }

    float acc[2][8][4] = {};
#pragma unroll
    for (int q = 0; q < 4; q++) {
        if (q == 0)      asm volatile("cp.async.wait_group 3;\n" ::: "memory");
        else if (q == 1) asm volatile("cp.async.wait_group 2;\n" ::: "memory");
        else if (q == 2) asm volatile("cp.async.wait_group 1;\n" ::: "memory");
        else             asm volatile("cp.async.wait_group 0;\n" ::: "memory");
        __syncthreads();
#pragma unroll
        for (int kt = 0; kt < 2; kt++) {
            const int kk = q * 2 + kt;
            uint32_t ah[2][4];
#pragma unroll
            for (int mf = 0; mf < 2; mf++) {
                const __half* p0 = sQh + (m0 + mf * 16 + g) * K1S + kk * 16 + 2 * ct;
                ah[mf][0] = *(const uint32_t*)p0;
                ah[mf][1] = *(const uint32_t*)(p0 + 8 * K1S);
                ah[mf][2] = *(const uint32_t*)(p0 + 8);
                ah[mf][3] = *(const uint32_t*)(p0 + 8 * K1S + 8);
            }
#pragma unroll
            for (int nf = 0; nf < 8; nf++) {
                const __half* kb = sKh + (n0 + nf * 8 + g) * K1S + kk * 16 + 2 * ct;
                uint32_t bh0 = *(const uint32_t*)kb;
                uint32_t bh1 = *(const uint32_t*)(kb + 8);
                const __half* kc = sKl + (n0 + nf * 8 + g) * K1S + kk * 16 + 2 * ct;
                uint32_t bl0 = *(const uint32_t*)kc;
                uint32_t bl1 = *(const uint32_t*)(kc + 8);
#pragma unroll
                for (int mf = 0; mf < 2; mf++) {
                    MMA_F16(acc[mf][nf], ah[mf][0], ah[mf][1], ah[mf][2], ah[mf][3], bh0, bh1);
                    MMA_F16(acc[mf][nf], ah[mf][0], ah[mf][1], ah[mf][2], ah[mf][3], bl0, bl1);
                }
            }
        }
    }

    // ---- epilogue: scale, mask, exp, fp32 E store, partial sums (R7-identical) ----
    const float mval = (VL == 0) ? 1.0f : 0.0f;
    const int jt = blockIdx.x * 4 + wn;        // 64-col block id (0..31)
#pragma unroll
    for (int mf = 0; mf < 2; mf++) {
#pragma unroll
        for (int h = 0; h < 2; h++) {
            const int row = m0 + mf * 16 + h * 8 + g;
            float* erow = eg + ((size_t)b * Qn + i0 + row) * Kn + j0 + n0;
            float se = 0.f;
#pragma unroll
            for (int nf = 0; nf < 8; nf++) {
                int j = j0 + n0 + nf * 8 + 2 * ct;
                float e0 = (j     < VL) ? __expf(acc[mf][nf][2 * h]     * SC_SCALE) : mval;
                float e1 = (j + 1 < VL) ? __expf(acc[mf][nf][2 * h + 1] * SC_SCALE) : mval;
                *(float2*)(erow + nf * 8 + 2 * ct) = make_float2(e0, e1);
                se += e0 + e1;
            }
            se += __shfl_xor_sync(0xffffffffu, se, 1);
            se += __shfl_xor_sync(0xffffffffu, se, 2);
            if (ct == 0)
                ps[((size_t)b * Qn + i0 + row) * 32 + jt] = se;
        }
    }
}

// ================= K1b: reduce partials -> 1/row sum =================
__global__ void __launch_bounds__(256)
reduce_kernel(const float* __restrict__ ps, float* __restrict__ iso)
{
    int i = blockIdx.x * 256 + threadIdx.x;
    const float4* s4 = (const float4*)(ps + (size_t)i * 32);
    float sum = 0.f;
#pragma unroll
    for (int t = 0; t < 8; t++) {
        float4 sv = s4[t];
        sum += (sv.x + sv.y) + (sv.z + sv.w);
    }
    iso[i] = 1.0f / sum;
}

// ================= K2: normalize + attn writeback + PV GEMM (2-term fp16) =================
#define PS 68     /* float stride, E tile (k-contiguous) */
#define VS 72     /* fp16 stride, Vt tile rows d, cols k  */
#define K2_OFF_S  0
#define K2_SZ_S   (128 * PS * 4)          /* 34816 */
#define K2_OFF_VH (K2_SZ_S)
#define K2_SZ_V   (128 * VS * 2)          /* 18432 */
#define K2_OFF_VL (K2_OFF_VH + K2_SZ_V)
#define K2_OFF_IV (K2_OFF_VL + K2_SZ_V)
#define K2_SMEM   (K2_OFF_IV + 128 * 4)   /* 72192 */

__global__ void __launch_bounds__(256, 2)
pv_kernel(float* __restrict__ att,                     // in: E values, out: attn
          const __half* __restrict__ vth, const __half* __restrict__ vtl,
          const float* __restrict__ isg,
          float* __restrict__ outg)
{
    extern __shared__ unsigned char sm[];
    float*  sS  = (float*)(sm + K2_OFF_S);
    __half* sVh = (__half*)(sm + K2_OFF_VH);
    __half* sVl = (__half*)(sm + K2_OFF_VL);
    float*  sIv = (float*)(sm + K2_OFF_IV);

    const int b  = blockIdx.y;
    const int i0 = blockIdx.x * 128;
    const int tid = threadIdx.x;
    const int w = tid >> 5, lane = tid & 31;
    const int g = lane >> 2, ct = lane & 3;
    const int wm = w >> 1, wn = w & 1;

    float* Sg = att + ((size_t)b * Qn + i0) * Kn;
    const __half* vh_g = vth + (size_t)b * Dn * Kn;
    const __half* vl_g = vtl + (size_t)b * Dn * Kn;
    uint32_t sS_u  = smem_u32(sS);
    uint32_t sVh_u = smem_u32(sVh);
    uint32_t sVl_u = smem_u32(sVl);

    if (tid < 128) sIv[tid] = isg[(size_t)b * Qn + i0 + tid];

    float ris[2][2];
#pragma unroll
    for (int mf = 0; mf < 2; mf++)
#pragma unroll
        for (int h = 0; h < 2; h++)
            ris[mf][h] = isg[(size_t)b * Qn + i0 + wm * 32 + mf * 16 + h * 8 + g];

    float acc[2][8][4] = {};

    for (int c0 = 0; c0 < Kn; c0 += 64) {
        __syncthreads();
#pragma unroll
        for (int rep = 0; rep < 8; rep++) {
            int idx = tid + rep * 256;
            int r = idx >> 4, c4 = idx & 15;
            cpasync16(sS_u + r * (PS * 4) + c4 * 16, Sg + (size_t)r * Kn + c0 + c4 * 4);
        }
#pragma unroll
        for (int rep = 0; rep < 8; rep++) {
            int arr = rep >> 2;
            int rem = tid + (rep & 3) * 256;
            int d = rem >> 3, c4 = rem & 7;
            if (arr == 0)
                cpasync16(sVh_u + d * (VS * 2) + c4 * 16, vh_g + (size_t)d * Kn + c0 + c4 * 8);
            else
                cpasync16(sVl_u + d * (VS * 2) + c4 * 16, vl_g + (size_t)d * Kn + c0 + c4 * 8);
        }
        CP_COMMIT; CP_WAIT0;
        __syncthreads();

        // normalized-attn writeback (each element exactly once, coalesced)
#pragma unroll
        for (int rep = 0; rep < 8; rep++) {
            int idx = tid + rep * 256;
            int r = idx >> 4, c4 = idx & 15;
            float iv = sIv[r];
            float4 e = *(const float4*)(sS + r * PS + c4 * 4);
            e.x *= iv; e.y *= iv; e.z *= iv; e.w *= iv;
            *(float4*)(Sg + (size_t)r * Kn + c0 + c4 * 4) = e;
        }

#pragma unroll
        for (int kk = 0; kk < 4; kk++) {
            uint32_t ah[2][4];
#pragma unroll
            for (int mf = 0; mf < 2; mf++) {
                const float* sp = sS + (wm * 32 + mf * 16 + g) * PS + kk * 16 + 2 * ct;
                float2 s0 = *(const float2*)sp;
                float2 s1 = *(const float2*)(sp + 8 * PS);
                float2 s2 = *(const float2*)(sp + 8);
                float2 s3 = *(const float2*)(sp + 8 * PS + 8);
                float i0v = ris[mf][0], i1v = ris[mf][1];
                ah[mf][0] = packh2(s0.x * i0v, s0.y * i0v);
                ah[mf][1] = packh2(s1.x * i1v, s1.y * i1v);
                ah[mf][2] = packh2(s2.x * i0v, s2.y * i0v);
                ah[mf][3] = packh2(s3.x * i1v, s3.y * i1v);
            }
#pragma unroll
            for (int nf = 0; nf < 8; nf++) {
                const __half* vb = sVh + (wn * 64 + nf * 8 + g) * VS + kk * 16 + 2 * ct;
                uint32_t bh0 = *(const uint32_t*)vb;
                uint32_t bh1 = *(const uint32_t*)(vb + 8);
                const __half* vc = sVl + (wn * 64 + nf * 8 + g) * VS + kk * 16 + 2 * ct;
                uint32_t bl0 = *(const uint32_t*)vc;
                uint32_t bl1 = *(const uint32_t*)(vc + 8);
#pragma unroll
                for (int mf = 0; mf < 2; mf++) {
                    MMA_F16(acc[mf][nf], ah[mf][0], ah[mf][1], ah[mf][2], ah[mf][3], bh0, bh1);
                    MMA_F16(acc[mf][nf], ah[mf][0], ah[mf][1], ah[mf][2], ah[mf][3], bl0, bl1);
                }
            }
        }
    }

    float* op = outg + ((size_t)b * Qn + i0) * Dn;
#pragma unroll
    for (int mf = 0; mf < 2; mf++)
#pragma unroll
        for (int nf = 0; nf < 8; nf++) {
            int row = wm * 32 + mf * 16 + g;
            int col = wn * 64 + nf * 8 + 2 * ct;
            *(float2*)(op + (size_t)row * Dn + col)       = make_float2(acc[mf][nf][0], acc[mf][nf][1]);
            *(float2*)(op + (size_t)(row + 8) * Dn + col) = make_float2(acc[mf][nf][2], acc[mf][nf][3]);
        }
}

// ================= launch =================
extern "C" void kernel_launch(void* const* d_in, const int* in_sizes, int n_in,
                              void* d_out, int out_size) {
    const float* q  = (const float*)d_in[0];
    const float* k  = (const float*)d_in[1];
    const float* v  = (const float*)d_in[2];
    const int*   vl = (const int*)d_in[3];
    float* out  = (float*)d_out;
    float* attn = out + (size_t)Bn * Qn * Dn;   // output tuple: (out, attn)

    void *p_qh, *p_kh, *p_kl, *p_vth, *p_vtl, *p_ps, *p_is;
    cudaGetSymbolAddress(&p_qh, g_qh);
    cudaGetSymbolAddress(&p_kh, g_kh);
    cudaGetSymbolAddress(&p_kl, g_kl);
    cudaGetSymbolAddress(&p_vth, g_vth);
    cudaGetSymbolAddress(&p_vtl, g_vtl);
    cudaGetSymbolAddress(&p_ps, g_ps);
    cudaGetSymbolAddress(&p_is, g_is);

    cudaFuncSetAttribute(scores_kernel, cudaFuncAttributeMaxDynamicSharedMemorySize, K1_SMEM);
    cudaFuncSetAttribute(pv_kernel,     cudaFuncAttributeMaxDynamicSharedMemorySize, K2_SMEM);

    const int n4 = Bn * Qn * Dn / 4;
    convert1_kernel<<<n4 / 256, 256>>>(q, (__half*)p_qh);
    convert2_kernel<<<n4 / 256, 256>>>(k, (__half*)p_kh, (__half*)p_kl);
    transpose_conv_kernel<<<dim3(Kn / 32, Dn / 32, Bn), 256>>>(v, (__half*)p_vth,
                                                               (__half*)p_vtl);

    scores_kernel<<<dim3(Kn / 256, Qn / 128, Bn), 512, K1_SMEM>>>(
        (const __half*)p_qh, (const __half*)p_kh, (const __half*)p_kl,
        vl, attn, (float*)p_ps);

    reduce_kernel<<<Bn * Qn / 256, 256>>>((const float*)p_ps, (float*)p_is);

    pv_kernel<<<dim3(Qn / 128, Bn), 256, K2_SMEM>>>(
        attn, (const __half*)p_vth, (const __half*)p_vtl,
        (const float*)p_is, out);
}

// round 16
// speedup vs baseline: 1.3483x; 1.0602x over previous
#include <cuda_runtime.h>
#include <cuda_fp16.h>
#include <cstdint>

#define Bn 64
#define Qn 2048
#define Kn 2048
#define Dn 128

// ---------------- scratch (device globals; no allocation) ----------------
__device__ __align__(256) __half g_qh[(size_t)Bn * Qn * Dn];          // Q fp16 (single)
__device__ __align__(256) __half g_kh[(size_t)Bn * Kn * Dn];          // K fp16 hi
__device__ __align__(256) __half g_kl[(size_t)Bn * Kn * Dn];          // K fp16 lo
__device__ __align__(256) __half g_vth[(size_t)Bn * Dn * Kn];         // V^T fp16 hi [b][d][k]
__device__ __align__(256) __half g_vtl[(size_t)Bn * Dn * Kn];         // V^T fp16 lo
__device__ __align__(256) __half g_e[(size_t)Bn * Qn * Kn];           // E fp16 (unnormalized)
__device__ __align__(256) float g_ps[(size_t)Bn * Qn * 32];   // partial sums per 64-col block
__device__ __align__(256) float g_is[(size_t)Bn * Qn];        // 1/row sum

// ---------------- helpers ----------------
#define MMA_F16(C, a0, a1, a2, a3, b0, b1)                                    \
  asm volatile(                                                               \
      "mma.sync.aligned.m16n8k16.row.col.f32.f16.f16.f32 "                    \
      "{%0,%1,%2,%3}, {%4,%5,%6,%7}, {%8,%9}, {%0,%1,%2,%3};\n"               \
      : "+f"(C[0]), "+f"(C[1]), "+f"(C[2]), "+f"(C[3])                        \
      : "r"(a0), "r"(a1), "r"(a2), "r"(a3), "r"(b0), "r"(b1))

#define LDSM_X4(r0, r1, r2, r3, a)                                            \
  asm volatile("ldmatrix.sync.aligned.m8n8.x4.shared.b16 {%0,%1,%2,%3}, [%4];" \
               : "=r"(r0), "=r"(r1), "=r"(r2), "=r"(r3) : "r"(a))

__device__ __forceinline__ uint32_t packh2(float x, float y) {
    __half2 h = __floats2half2_rn(x, y);
    return *reinterpret_cast<uint32_t*>(&h);
}
__device__ __forceinline__ void splith(float x, float y, uint32_t& h, uint32_t& l) {
    __half2 hh = __floats2half2_rn(x, y);
    float hx = __low2float(hh);
    float hy = __high2float(hh);
    __half2 ll = __floats2half2_rn(x - hx, y - hy);
    h = *reinterpret_cast<uint32_t*>(&hh);
    l = *reinterpret_cast<uint32_t*>(&ll);
}
__device__ __forceinline__ uint32_t smem_u32(const void* p) {
    return (uint32_t)__cvta_generic_to_shared(p);
}
__device__ __forceinline__ void cpasync16(uint32_t dst, const void* src) {
    asm volatile("cp.async.cg.shared.global [%0], [%1], 16;\n" :: "r"(dst), "l"(src));
}
#define CP_COMMIT asm volatile("cp.async.commit_group;\n" ::: "memory")
#define CP_WAIT0  asm volatile("cp.async.wait_group 0;\n" ::: "memory")

// ================= K0a: fp32 -> single fp16 =================
__global__ void __launch_bounds__(256)
convert1_kernel(const float* __restrict__ x, __half* __restrict__ h)
{
    int i = blockIdx.x * 256 + threadIdx.x;
    float4 v = ((const float4*)x)[i];
    ((uint2*)h)[i] = make_uint2(packh2(v.x, v.y), packh2(v.z, v.w));
}

// ================= K0b: fp32 -> (hi, lo) fp16 =================
__global__ void __launch_bounds__(256)
convert2_kernel(const float* __restrict__ x, __half* __restrict__ h,
                __half* __restrict__ l)
{
    int i = blockIdx.x * 256 + threadIdx.x;
    float4 v = ((const float4*)x)[i];
    uint32_t h0, l0, h1, l1;
    splith(v.x, v.y, h0, l0);
    splith(v.z, v.w, h1, l1);
    ((uint2*)h)[i] = make_uint2(h0, h1);
    ((uint2*)l)[i] = make_uint2(l0, l1);
}

// ================= K0c: V fp32 [b][k][d] -> fp16 hi/lo [b][d][k] =================
__global__ void __launch_bounds__(256)
transpose_conv_kernel(const float* __restrict__ v,
                      __half* __restrict__ th, __half* __restrict__ tl)
{
    __shared__ float t[32][33];
    const int b  = blockIdx.z;
    const int k0 = blockIdx.x * 32;
    const int d0 = blockIdx.y * 32;
    const int tx = threadIdx.x & 31;
    const int ty = threadIdx.x >> 5;
#pragma unroll
    for (int i = 0; i < 4; i++) {
        int k = ty + i * 8;
        t[k][tx] = v[((size_t)b * Kn + k0 + k) * Dn + d0 + tx];
    }
    __syncthreads();
#pragma unroll
    for (int i = 0; i < 4; i++) {
        int d = ty + i * 8;
        float x = t[tx][d];
        __half hb = __float2half_rn(x);
        __half lb = __float2half_rn(x - __half2float(hb));
        size_t o = ((size_t)b * Dn + d0 + d) * Kn + k0 + tx;
        th[o] = hb;
        tl[o] = lb;
    }
}

// ================= K1: E = exp(masked scores) -> fp16 + partial row sums =================
// 512 threads, CTA tile M=128 x N=256, 4-quarter cp.async pipeline,
// manual LDS frag loads, 2-term fp16 mma (qh*kh + qh*kl).
#define K1S 136                    /* fp16 row stride (272 B) */
#define OFF_QH 0
#define OFF_KH (128 * K1S * 2)                 /* 34816 */
#define OFF_KL (OFF_KH + 256 * K1S * 2)        /* 104448 */
#define K1_SMEM (OFF_KL + 256 * K1S * 2)       /* 174080 */
#define SC_SCALE 0.08838834764831845f

__global__ void __launch_bounds__(512, 1)
scores_kernel(const __half* __restrict__ qh, const __half* __restrict__ kh,
              const __half* __restrict__ kl, const int* __restrict__ vlg,
              __half* __restrict__ eg, float* __restrict__ ps)
{
    extern __shared__ unsigned char sm[];
    __half* sQh = (__half*)(sm + OFF_QH);
    __half* sKh = (__half*)(sm + OFF_KH);
    __half* sKl = (__half*)(sm + OFF_KL);
    const uint32_t uQh = smem_u32(sQh), uKh = smem_u32(sKh), uKl = smem_u32(sKl);

    const int b  = blockIdx.z;
    const int i0 = blockIdx.y * 128;
    const int j0 = blockIdx.x * 256;
    const int tid = threadIdx.x;
    const int w = tid >> 5, lane = tid & 31;
    const int g = lane >> 2, ct = lane & 3;
    const int wm = w >> 2, wn = w & 3;        // 4x4 warp grid, 32x64 warp tiles
    const int m0 = wm * 32, n0 = wn * 64;
    const int VL = vlg[b];

    const __half* bq = qh + ((size_t)b * Qn + i0) * Dn;
    const __half* bkh = kh + ((size_t)b * Kn + j0) * Dn;
    const __half* bkl = kl + ((size_t)b * Kn + j0) * Dn;

    // 4 commit groups, one per D-quarter (cols q*32 .. q*32+31)
#pragma unroll
    for (int q = 0; q < 4; q++) {
        {   // Qh: 512 ops
            int r = tid >> 2, cc = tid & 3;
            int dsto = r * (K1S * 2) + (q * 4 + cc) * 16;
            cpasync16(uQh + dsto, bq + (size_t)r * Dn + q * 32 + cc * 8);
        }
#pragma unroll
        for (int rep = 0; rep < 2; rep++) {   // Kh, Kl: 1024 ops each
            int idx = tid + rep * 512;
            int r = idx >> 2, cc = idx & 3;
            int dsto = r * (K1S * 2) + (q * 4 + cc) * 16;
            size_t srco = (size_t)r * Dn + q * 32 + cc * 8;
            cpasync16(uKh + dsto, bkh + srco);
            cpasync16(uKl + dsto, bkl + srco);
        }
        CP_COMMIT;
    }

    float acc[2][8][4] = {};
#pragma unroll
    for (int q = 0; q < 4; q++) {
        if (q == 0)      asm volatile("cp.async.wait_group 3;\n" ::: "memory");
        else if (q == 1) asm volatile("cp.async.wait_group 2;\n" ::: "memory");
        else if (q == 2) asm volatile("cp.async.wait_group 1;\n" ::: "memory");
        else             asm volatile("cp.async.wait_group 0;\n" ::: "memory");
        __syncthreads();
#pragma unroll
        for (int kt = 0; kt < 2; kt++) {
            const int kk = q * 2 + kt;
            uint32_t ah[2][4];
#pragma unroll
            for (int mf = 0; mf < 2; mf++) {
                const __half* p0 = sQh + (m0 + mf * 16 + g) * K1S + kk * 16 + 2 * ct;
                ah[mf][0] = *(const uint32_t*)p0;
                ah[mf][1] = *(const uint32_t*)(p0 + 8 * K1S);
                ah[mf][2] = *(const uint32_t*)(p0 + 8);
                ah[mf][3] = *(const uint32_t*)(p0 + 8 * K1S + 8);
            }
#pragma unroll
            for (int nf = 0; nf < 8; nf++) {
                const __half* kb = sKh + (n0 + nf * 8 + g) * K1S + kk * 16 + 2 * ct;
                uint32_t bh0 = *(const uint32_t*)kb;
                uint32_t bh1 = *(const uint32_t*)(kb + 8);
                const __half* kc = sKl + (n0 + nf * 8 + g) * K1S + kk * 16 + 2 * ct;
                uint32_t bl0 = *(const uint32_t*)kc;
                uint32_t bl1 = *(const uint32_t*)(kc + 8);
#pragma unroll
                for (int mf = 0; mf < 2; mf++) {
                    MMA_F16(acc[mf][nf], ah[mf][0], ah[mf][1], ah[mf][2], ah[mf][3], bh0, bh1);
                    MMA_F16(acc[mf][nf], ah[mf][0], ah[mf][1], ah[mf][2], ah[mf][3], bl0, bl1);
                }
            }
        }
    }

    // ---- epilogue: scale, mask, exp, fp16 E store, partial sums ----
    const float mval = (VL == 0) ? 1.0f : 0.0f;
    const int jt = blockIdx.x * 4 + wn;        // 64-col block id (0..31)
#pragma unroll
    for (int mf = 0; mf < 2; mf++) {
#pragma unroll
        for (int h = 0; h < 2; h++) {
            const int row = m0 + mf * 16 + h * 8 + g;
            __half* erow = eg + ((size_t)b * Qn + i0 + row) * Kn + j0 + n0;
            float se = 0.f;
#pragma unroll
            for (int nf = 0; nf < 8; nf++) {
                int j = j0 + n0 + nf * 8 + 2 * ct;
                float e0 = (j     < VL) ? __expf(acc[mf][nf][2 * h]     * SC_SCALE) : mval;
                float e1 = (j + 1 < VL) ? __expf(acc[mf][nf][2 * h + 1] * SC_SCALE) : mval;
                *(uint32_t*)(erow + nf * 8 + 2 * ct) = packh2(e0, e1);
                se += e0 + e1;
            }
            se += __shfl_xor_sync(0xffffffffu, se, 1);
            se += __shfl_xor_sync(0xffffffffu, se, 2);
            if (ct == 0)
                ps[((size_t)b * Qn + i0 + row) * 32 + jt] = se;
        }
    }
}

// ================= K1b: reduce partials -> 1/row sum =================
__global__ void __launch_bounds__(256)
reduce_kernel(const float* __restrict__ ps, float* __restrict__ iso)
{
    int i = blockIdx.x * 256 + threadIdx.x;
    const float4* s4 = (const float4*)(ps + (size_t)i * 32);
    float sum = 0.f;
#pragma unroll
    for (int t = 0; t < 8; t++) {
        float4 sv = s4[t];
        sum += (sv.x + sv.y) + (sv.z + sv.w);
    }
    iso[i] = 1.0f / sum;
}

// ================= K2: attn writeback + PV GEMM (pure LDSM + fp16 mma) =================
#define PS2 72    /* fp16 stride, E tile (144 B row) */
#define VS 72     /* fp16 stride, Vt tiles           */
#define K2_OFF_E  0
#define K2_SZ_E   (128 * PS2 * 2)          /* 18432 */
#define K2_OFF_VH (K2_SZ_E)
#define K2_OFF_VL (K2_OFF_VH + 128 * VS * 2)
#define K2_OFF_IV (K2_OFF_VL + 128 * VS * 2)
#define K2_SMEM   (K2_OFF_IV + 128 * 4)    /* 55808 */

__global__ void __launch_bounds__(256, 2)
pv_kernel(const __half* __restrict__ eg,
          const __half* __restrict__ vth, const __half* __restrict__ vtl,
          const float* __restrict__ isg,
          float* __restrict__ att, float* __restrict__ outg)
{
    extern __shared__ unsigned char sm[];
    __half* sE  = (__half*)(sm + K2_OFF_E);
    __half* sVh = (__half*)(sm + K2_OFF_VH);
    __half* sVl = (__half*)(sm + K2_OFF_VL);
    float*  sIv = (float*)(sm + K2_OFF_IV);

    const int b  = blockIdx.y;
    const int i0 = blockIdx.x * 128;
    const int tid = threadIdx.x;
    const int w = tid >> 5, lane = tid & 31;
    const int g = lane >> 2, ct = lane & 3;
    const int wm = w >> 1, wn = w & 1;

    const __half* e_g = eg + ((size_t)b * Qn + i0) * Kn;
    const __half* vh_g = vth + (size_t)b * Dn * Kn;
    const __half* vl_g = vtl + (size_t)b * Dn * Kn;
    float* Ag = att + ((size_t)b * Qn + i0) * Kn;
    uint32_t uE  = smem_u32(sE);
    uint32_t uVh = smem_u32(sVh);
    uint32_t uVl = smem_u32(sVl);

    if (tid < 128) sIv[tid] = isg[(size_t)b * Qn + i0 + tid];

    float ris[2][2];
#pragma unroll
    for (int mf = 0; mf < 2; mf++)
#pragma unroll
        for (int h = 0; h < 2; h++)
            ris[mf][h] = isg[(size_t)b * Qn + i0 + wm * 32 + mf * 16 + h * 8 + g];

    // ldmatrix bases
    const int lr = lane & 15;
    const int lc = (lane >> 4) << 3;
    const uint32_t aE  = uE  + ((wm * 32 + lr) * PS2 + lc) * 2;
    const uint32_t aVh = uVh + ((wn * 64 + lr) * VS + lc) * 2;
    const uint32_t aVl = uVl + ((wn * 64 + lr) * VS + lc) * 2;
    const uint32_t MSTEP2 = 16 * PS2 * 2;   // 2304 bytes

    float acc[2][8][4] = {};

    for (int c0 = 0; c0 < Kn; c0 += 64) {
        __syncthreads();
        // E tile: 128 rows x 64 fp16
#pragma unroll
        for (int rep = 0; rep < 4; rep++) {
            int idx = tid + rep * 256;      // 0..1023 = 128 rows x 8 chunks
            int r = idx >> 3, c8 = idx & 7;
            cpasync16(uE + r * (PS2 * 2) + c8 * 16, e_g + (size_t)r * Kn + c0 + c8 * 8);
        }
        // Vt tiles: 128 d-rows x 64 fp16 each (hi/lo)
#pragma unroll
        for (int rep = 0; rep < 4; rep++) {
            int idx = tid + rep * 256;
            int d = idx >> 3, c8 = idx & 7;
            uint32_t dsto = d * (VS * 2) + c8 * 16;
            size_t srco = (size_t)d * Kn + c0 + c8 * 8;
            cpasync16(uVh + dsto, vh_g + srco);
            cpasync16(uVl + dsto, vl_g + srco);
        }
        CP_COMMIT; CP_WAIT0;
        __syncthreads();

        // attn writeback: attn = E * inv, coalesced float4 stores
#pragma unroll
        for (int rep = 0; rep < 8; rep++) {
            int idx = tid + rep * 256;      // 0..2047 = 128 rows x 16 quad-cols
            int r = idx >> 4, c4 = idx & 15;
            float iv = sIv[r];
            const __half2* ep = (const __half2*)(sE + r * PS2 + c4 * 4);
            float2 e0 = __half22float2(ep[0]);
            float2 e1 = __half22float2(ep[1]);
            float4 o;
            o.x = e0.x * iv;
            o.y = e0.y * iv;
            o.z = e1.x * iv;
            o.w = e1.y * iv;
            *(float4*)(Ag + (size_t)r * Kn + c0 + c4 * 4) = o;
        }

#pragma unroll
        for (int kk = 0; kk < 4; kk++) {
            const uint32_t co = kk * 32;
            uint32_t ah[2][4];
            LDSM_X4(ah[0][0], ah[0][1], ah[0][2], ah[0][3], aE + co);
            LDSM_X4(ah[1][0], ah[1][1], ah[1][2], ah[1][3], aE + MSTEP2 + co);
#pragma unroll
            for (int nf2 = 0; nf2 < 4; nf2++) {
                uint32_t bh[4], bl[4];
                LDSM_X4(bh[0], bh[1], bh[2], bh[3], aVh + nf2 * MSTEP2 + co);
                LDSM_X4(bl[0], bl[1], bl[2], bl[3], aVl + nf2 * MSTEP2 + co);
#pragma unroll
                for (int mf = 0; mf < 2; mf++) {
                    MMA_F16(acc[mf][2 * nf2],     ah[mf][0], ah[mf][1], ah[mf][2], ah[mf][3], bh[0], bh[2]);
                    MMA_F16(acc[mf][2 * nf2],     ah[mf][0], ah[mf][1], ah[mf][2], ah[mf][3], bl[0], bl[2]);
                    MMA_F16(acc[mf][2 * nf2 + 1], ah[mf][0], ah[mf][1], ah[mf][2], ah[mf][3], bh[1], bh[3]);
                    MMA_F16(acc[mf][2 * nf2 + 1], ah[mf][0], ah[mf][1], ah[mf][2], ah[mf][3], bl[1], bl[3]);
                }
            }
        }
    }

    // out = acc * inv (normalization folded into accumulator epilogue)
    float* op = outg + ((size_t)b * Qn + i0) * Dn;
#pragma unroll
    for (int mf = 0; mf < 2; mf++)
#pragma unroll
        for (int nf = 0; nf < 8; nf++) {
            int row = wm * 32 + mf * 16 + g;
            int col = wn * 64 + nf * 8 + 2 * ct;
            float i0v = ris[mf][0], i1v = ris[mf][1];
            *(float2*)(op + (size_t)row * Dn + col) =
                make_float2(acc[mf][nf][0] * i0v, acc[mf][nf][1] * i0v);
            *(float2*)(op + (size_t)(row + 8) * Dn + col) =
                make_float2(acc[mf][nf][2] * i1v, acc[mf][nf][3] * i1v);
        }
}

// ================= launch =================
extern "C" void kernel_launch(void* const* d_in, const int* in_sizes, int n_in,
                              void* d_out, int out_size) {
    const float* q  = (const float*)d_in[0];
    const float* k  = (const float*)d_in[1];
    const float* v  = (const float*)d_in[2];
    const int*   vl = (const int*)d_in[3];
    float* out  = (float*)d_out;
    float* attn = out + (size_t)Bn * Qn * Dn;   // output tuple: (out, attn)

    void *p_qh, *p_kh, *p_kl, *p_vth, *p_vtl, *p_e, *p_ps, *p_is;
    cudaGetSymbolAddress(&p_qh, g_qh);
    cudaGetSymbolAddress(&p_kh, g_kh);
    cudaGetSymbolAddress(&p_kl, g_kl);
    cudaGetSymbolAddress(&p_vth, g_vth);
    cudaGetSymbolAddress(&p_vtl, g_vtl);
    cudaGetSymbolAddress(&p_e,  g_e);
    cudaGetSymbolAddress(&p_ps, g_ps);
    cudaGetSymbolAddress(&p_is, g_is);

    cudaFuncSetAttribute(scores_kernel, cudaFuncAttributeMaxDynamicSharedMemorySize, K1_SMEM);
    cudaFuncSetAttribute(pv_kernel,     cudaFuncAttributeMaxDynamicSharedMemorySize, K2_SMEM);

    const int n4 = Bn * Qn * Dn / 4;
    convert1_kernel<<<n4 / 256, 256>>>(q, (__half*)p_qh);
    convert2_kernel<<<n4 / 256, 256>>>(k, (__half*)p_kh, (__half*)p_kl);
    transpose_conv_kernel<<<dim3(Kn / 32, Dn / 32, Bn), 256>>>(v, (__half*)p_vth,
                                                               (__half*)p_vtl);

    scores_kernel<<<dim3(Kn / 256, Qn / 128, Bn), 512, K1_SMEM>>>(
        (const __half*)p_qh, (const __half*)p_kh, (const __half*)p_kl,
        vl, (__half*)p_e, (float*)p_ps);

    reduce_kernel<<<Bn * Qn / 256, 256>>>((const float*)p_ps, (float*)p_is);

    pv_kernel<<<dim3(Qn / 128, Bn), 256, K2_SMEM>>>(
        (const __half*)p_e, (const __half*)p_vth, (const __half*)p_vtl,
        (const float*)p_is, attn, out);
}